// round 1
// baseline (speedup 1.0000x reference)
#include <cuda_runtime.h>
#include <cuda_bf16.h>
#include <math.h>

// ---------------- problem constants ----------------
// B=1024, H=512, half=256
// conv1: 2->64, 3x3, s1 p1, 32x32 -> 32x32
// conv2: 64->128, 3x3, s2 p1, 32x32 -> 16x16
// conv3: 128->256, 16x16 valid -> 1x1  (GEMM 1024x256x32768)
// GRU: x[1024,512] -> gi = x @ Wih^T, gh = h0 @ Whh^T, gates.

#define BATCH 1024
#define LEAK 0.01f

// ---------------- device scratch ----------------
__device__ float g_h1[1024 * 64 * 32 * 32];    // 256 MB
__device__ float g_h2[1024 * 128 * 16 * 16];   // 128 MB
__device__ float g_w2t[64 * 9 * 128];          // transposed conv2 weights [ic][k][oc]
__device__ float g_part[16 * 1024 * 256];      // conv3 split-K partials
__device__ float g_x[1024 * 512];              // GRU input (prevec | heightvec)
__device__ float g_gi[1024 * 1536];
__device__ float g_gh[1024 * 1536];

__device__ __forceinline__ float leaky(float v) { return v >= 0.f ? v : LEAK * v; }

// ---------------- conv1: 2->64 3x3 p1, + leaky ----------------
// grid 4096 (4 blocks per image), block 256, one output spatial position/thread.
__global__ void __launch_bounds__(256) conv1_kernel(const float* __restrict__ hm,
                                                    const float* __restrict__ w,
                                                    const float* __restrict__ bias) {
    int b = blockIdx.x >> 2;
    int p = ((blockIdx.x & 3) << 8) + threadIdx.x;   // 0..1023
    int oy = p >> 5, ox = p & 31;

    __shared__ float in_s[2048];          // 2x32x32
    __shared__ float w_s[64 * 20];        // 18 weights per oc, padded to 20 (f4 aligned)
    __shared__ float b_s[64];

    const float4* src = (const float4*)(hm + (size_t)b * 2048);
    float4* dst = (float4*)in_s;
    for (int i = threadIdx.x; i < 512; i += 256) dst[i] = src[i];
    for (int i = threadIdx.x; i < 64 * 20; i += 256) {
        int oc = i / 20, k = i % 20;
        w_s[i] = (k < 18) ? w[oc * 18 + k] : 0.f;
    }
    if (threadIdx.x < 64) b_s[threadIdx.x] = bias[threadIdx.x];
    __syncthreads();

    float v[18];
#pragma unroll
    for (int c = 0; c < 2; c++)
#pragma unroll
        for (int ky = 0; ky < 3; ky++)
#pragma unroll
            for (int kx = 0; kx < 3; kx++) {
                int iy = oy - 1 + ky, ix = ox - 1 + kx;
                float t = 0.f;
                if (iy >= 0 && iy < 32 && ix >= 0 && ix < 32) t = in_s[c * 1024 + iy * 32 + ix];
                v[c * 9 + ky * 3 + kx] = t;
            }

    float* out = g_h1 + (size_t)b * 65536 + p;
    for (int oc = 0; oc < 64; oc++) {
        const float4* wp = (const float4*)(w_s + oc * 20);
        float4 w0 = wp[0], w1 = wp[1], w2 = wp[2], w3 = wp[3];
        float2 w4 = *(const float2*)(w_s + oc * 20 + 16);
        float acc = b_s[oc];
        acc += v[0] * w0.x + v[1] * w0.y + v[2] * w0.z + v[3] * w0.w;
        acc += v[4] * w1.x + v[5] * w1.y + v[6] * w1.z + v[7] * w1.w;
        acc += v[8] * w2.x + v[9] * w2.y + v[10] * w2.z + v[11] * w2.w;
        acc += v[12] * w3.x + v[13] * w3.y + v[14] * w3.z + v[15] * w3.w;
        acc += v[16] * w4.x + v[17] * w4.y;
        out[oc * 1024] = leaky(acc);
    }
}

// ---------------- conv2 weight transpose: [oc][ic][k] -> [ic][k][oc] ----------------
__global__ void __launch_bounds__(256) w2t_kernel(const float* __restrict__ w) {
    int t = blockIdx.x * 256 + threadIdx.x;
    if (t >= 64 * 9 * 128) return;
    int ic = t / 1152;
    int rem = t - ic * 1152;
    int k = rem >> 7;
    int oc = rem & 127;
    g_w2t[t] = w[oc * 576 + ic * 9 + k];
}

// ---------------- conv2: 64->128 3x3 s2 p1, + leaky ----------------
// grid 2048 (image, oc-half), block 256. Thread tile: 8 oc x 8 spatial.
// warp = one 8-oc group, lane -> spatial: p = lane + 32*q (stores coalesce).
__global__ void __launch_bounds__(256, 2) conv2_kernel(const float* __restrict__ bias) {
    int b = blockIdx.x >> 1;
    int ocb = (blockIdx.x & 1) << 6;   // 0 or 64
    int tid = threadIdx.x;
    int lane = tid & 31, wrp = tid >> 5;
    int ox = lane & 15;
    int oy0 = lane >> 4;               // 0/1

    __shared__ float in_s[1024];       // one input channel 32x32
    __shared__ float w_s[576];         // [k][oc_local 64]

    float acc[8][8];
#pragma unroll
    for (int o = 0; o < 8; o++)
#pragma unroll
        for (int q = 0; q < 8; q++) acc[o][q] = 0.f;

    const float* inG = g_h1 + (size_t)b * 65536;

    for (int ic = 0; ic < 64; ic++) {
        __syncthreads();
        ((float4*)in_s)[tid] = ((const float4*)(inG + ic * 1024))[tid];
        for (int i = tid; i < 576; i += 256)
            w_s[i] = g_w2t[ic * 1152 + ((i >> 6) << 7) + ocb + (i & 63)];
        __syncthreads();

#pragma unroll
        for (int k = 0; k < 9; k++) {
            int ky = k / 3, kx = k - 3 * (k / 3);
            int ix = 2 * ox - 1 + kx;
            float vv[8];
#pragma unroll
            for (int q = 0; q < 8; q++) {
                int oy = oy0 + 2 * q;
                int iy = 2 * oy - 1 + ky;
                float t = 0.f;
                if (iy >= 0 && ix >= 0) t = in_s[iy * 32 + ix];  // iy<32, ix<32 always
                vv[q] = t;
            }
            float4 wa = *(const float4*)(w_s + k * 64 + wrp * 8);
            float4 wb = *(const float4*)(w_s + k * 64 + wrp * 8 + 4);
            float wr[8] = {wa.x, wa.y, wa.z, wa.w, wb.x, wb.y, wb.z, wb.w};
#pragma unroll
            for (int o = 0; o < 8; o++)
#pragma unroll
                for (int q = 0; q < 8; q++) acc[o][q] += wr[o] * vv[q];
        }
    }

    float* outG = g_h2 + (size_t)b * 32768;
#pragma unroll
    for (int o = 0; o < 8; o++) {
        int oc = ocb + wrp * 8 + o;
        float bz = bias[oc];
#pragma unroll
        for (int q = 0; q < 8; q++) {
            float r = acc[o][q] + bz;
            outG[oc * 256 + q * 32 + lane] = leaky(r);
        }
    }
}

// ---------------- generic GEMM: C[m][n] = sum_k A[m][k]*B[n][k] ----------------
// 64x64 tile per CTA, 256 threads, 4x4 per thread, kc=32.
// blockIdx.x -> m tile, .y -> n tile, .z -> k chunk. C += kz*cStride.
__global__ void __launch_bounds__(256) gemm_tn_kernel(const float* __restrict__ A,
                                                      const float* __restrict__ B,
                                                      float* __restrict__ C,
                                                      int lda, int ldb, int ldc,
                                                      int kLen, long long cStride) {
    __shared__ float As[32][68];
    __shared__ float Bs[32][68];
    int m0 = blockIdx.x * 64, n0 = blockIdx.y * 64;
    int kz = blockIdx.z;
    long long k0 = (long long)kz * kLen;
    int tid = threadIdx.x;
    int tx = tid & 15, ty = tid >> 4;

    float acc[4][4] = {};
    const float* Ap = A + (size_t)m0 * lda + k0;
    const float* Bp = B + (size_t)n0 * ldb + k0;

    for (int kk = 0; kk < kLen; kk += 32) {
#pragma unroll
        for (int h = 0; h < 2; h++) {
            int idx = tid + h * 256;       // 0..511
            int r = idx >> 3, c4 = idx & 7;
            float4 a = *(const float4*)(Ap + (size_t)r * lda + kk + c4 * 4);
            As[c4 * 4 + 0][r] = a.x; As[c4 * 4 + 1][r] = a.y;
            As[c4 * 4 + 2][r] = a.z; As[c4 * 4 + 3][r] = a.w;
            float4 bv = *(const float4*)(Bp + (size_t)r * ldb + kk + c4 * 4);
            Bs[c4 * 4 + 0][r] = bv.x; Bs[c4 * 4 + 1][r] = bv.y;
            Bs[c4 * 4 + 2][r] = bv.z; Bs[c4 * 4 + 3][r] = bv.w;
        }
        __syncthreads();
#pragma unroll
        for (int k2 = 0; k2 < 32; k2++) {
            float4 a4 = *(const float4*)&As[k2][tx * 4];
            float4 b4 = *(const float4*)&Bs[k2][ty * 4];
            float av[4] = {a4.x, a4.y, a4.z, a4.w};
            float bw[4] = {b4.x, b4.y, b4.z, b4.w};
#pragma unroll
            for (int i = 0; i < 4; i++)
#pragma unroll
                for (int j = 0; j < 4; j++) acc[i][j] += av[i] * bw[j];
        }
        __syncthreads();
    }

    float* Cw = C + (long long)kz * cStride;
#pragma unroll
    for (int i = 0; i < 4; i++)
#pragma unroll
        for (int j = 0; j < 4; j++)
            Cw[(size_t)(m0 + tx * 4 + i) * ldc + n0 + ty * 4 + j] = acc[i][j];
}

// ---------------- split-K reduce + conv3 bias/leaky + prebox -> g_x ----------------
__global__ void __launch_bounds__(256) build_x_kernel(const float* __restrict__ pre_box,
                                                      const float* __restrict__ pw,
                                                      const float* __restrict__ pb,
                                                      const float* __restrict__ c3b) {
    int t = blockIdx.x * 256 + threadIdx.x;   // 0 .. 1024*512-1
    int b = t >> 9, j = t & 511;
    float s;
    if (j < 256) {
        s = pb[j] + pre_box[b * 3] * pw[j * 3] + pre_box[b * 3 + 1] * pw[j * 3 + 1] +
            pre_box[b * 3 + 2] * pw[j * 3 + 2];
    } else {
        int n = j - 256;
        s = 0.f;
#pragma unroll
        for (int kz = 0; kz < 16; kz++) s += g_part[kz * 262144 + b * 256 + n];
        s += c3b[n];
        s = leaky(s);
    }
    g_x[t] = s;
}

// ---------------- GRU gates ----------------
__device__ __forceinline__ float sigmoid_t(float x) { return 0.5f + 0.5f * tanhf(0.5f * x); }

__global__ void __launch_bounds__(256) gates_kernel(const float* __restrict__ hh,
                                                    const float* __restrict__ bih,
                                                    const float* __restrict__ bhh,
                                                    float* __restrict__ out) {
    int t = blockIdx.x * 256 + threadIdx.x;   // 0 .. 1024*512-1
    int b = t >> 9, j = t & 511;
    size_t base = (size_t)b * 1536 + j;
    float ir = g_gi[base] + bih[j];
    float iz = g_gi[base + 512] + bih[512 + j];
    float inn = g_gi[base + 1024] + bih[1024 + j];
    float hr = g_gh[base] + bhh[j];
    float hz = g_gh[base + 512] + bhh[512 + j];
    float hn = g_gh[base + 1024] + bhh[1024 + j];
    float r = sigmoid_t(ir + hr);
    float z = sigmoid_t(iz + hz);
    float n = tanhf(inn + r * hn);
    float h0 = hh[t];
    float hnew = (1.f - z) * n + z * h0;
    out[t] = hnew;
    out[524288 + t] = hnew;   // new_hh
}

// ---------------- launch ----------------
extern "C" void kernel_launch(void* const* d_in, const int* in_sizes, int n_in,
                              void* d_out, int out_size) {
    (void)in_sizes; (void)n_in; (void)out_size;
    const float* pre_box = (const float*)d_in[0];
    const float* hm      = (const float*)d_in[1];
    const float* last_hh = (const float*)d_in[2];
    const float* pw      = (const float*)d_in[3];
    const float* pb      = (const float*)d_in[4];
    const float* c1w     = (const float*)d_in[5];
    const float* c1b     = (const float*)d_in[6];
    const float* c2w     = (const float*)d_in[7];
    const float* c2b     = (const float*)d_in[8];
    const float* c3w     = (const float*)d_in[9];
    const float* c3b     = (const float*)d_in[10];
    const float* wih     = (const float*)d_in[11];
    const float* whh     = (const float*)d_in[12];
    const float* bih     = (const float*)d_in[13];
    const float* bhh     = (const float*)d_in[14];
    float* out = (float*)d_out;

    float *p_h2, *p_part, *p_x, *p_gi, *p_gh;
    cudaGetSymbolAddress((void**)&p_h2, g_h2);
    cudaGetSymbolAddress((void**)&p_part, g_part);
    cudaGetSymbolAddress((void**)&p_x, g_x);
    cudaGetSymbolAddress((void**)&p_gi, g_gi);
    cudaGetSymbolAddress((void**)&p_gh, g_gh);

    conv1_kernel<<<4096, 256>>>(hm, c1w, c1b);
    w2t_kernel<<<288, 256>>>(c2w);
    conv2_kernel<<<2048, 256>>>(c2b);

    // conv3 as GEMM 1024x256x32768, split-K 16 chunks of 2048
    gemm_tn_kernel<<<dim3(16, 4, 16), 256>>>(p_h2, c3w, p_part,
                                             32768, 32768, 256, 2048, 262144LL);
    build_x_kernel<<<2048, 256>>>(pre_box, pw, pb, c3b);

    // GRU GEMMs: 1024x1536x512
    gemm_tn_kernel<<<dim3(16, 24, 1), 256>>>(p_x, wih, p_gi, 512, 512, 1536, 512, 0LL);
    gemm_tn_kernel<<<dim3(16, 24, 1), 256>>>(last_hh, whh, p_gh, 512, 512, 1536, 512, 0LL);

    gates_kernel<<<2048, 256>>>(last_hh, bih, bhh, out);
}